// round 15
// baseline (speedup 1.0000x reference)
#include <cuda_runtime.h>
#include <cuda_fp16.h>
#include <cstdint>

// MorphLayer == conv2d(x, exp(k1)-exp(k2), VALID 3x3) + bias  (exact reduction)
// B=32 C=64 H=W=64 -> Ho=Wo=62, F=128.
// HMMA implicit-GEMM, single fp16 product, fp32 acc.
// R15 = R14 main (swapped operands, cp.async slab, STG.64 epilogue) with the
// prep (W transform + x transpose->fp16 swizzled) FUSED into the same kernel:
// phase 0 runs cooperatively across the single 296-CTA wave, then a
// replay-safe grid barrier (monotonic generation counter), then phase 1.

#define Hn  64
#define Wn  64
#define HOn 62
#define WOn 62
#define Fn  128
#define Cn  64

#define SLAB_ROWS  258                     // 4 ring slots * 64 + 2 pad rows
#define SLAB_BYTES (SLAB_ROWS * 128)       // 33024
#define WOFF       SLAB_BYTES
#define WRES_BYTES (9 * 64 * 128)          // 73728
#define SMEM_TOTAL (WOFF + WRES_BYTES)     // 106752 -> 2 CTAs/SM

#define JOBS_PER_HALF 992                  // 31 h-tiles * 32 batch
#define NCTA_PER_HALF 148
#define NCTA_TOTAL    296
#define JOBS_PER_CTA  7

// fp16 weights, SW128-swizzled: [tap][f=128][c=64]
__device__ __align__(16) unsigned char g_W[9 * 16384];
// fp16 x, transposed + per-row swizzled: [bz][h][w] -> 128B row of 64 c
__device__ __align__(16) unsigned char g_xT[32 * 64 * 64 * 128];
// monotonic grid-barrier counter (never reset; generation = ctr / 296)
__device__ unsigned g_bar = 0;

__device__ __forceinline__ uint32_t smem_u32(const void* p) {
    uint32_t a;
    asm("{ .reg .u64 t; cvta.to.shared.u64 t, %1; cvt.u32.u64 %0, t; }" : "=r"(a) : "l"(p));
    return a;
}

#define LDSM4(r, addr)                                                          \
    asm volatile("ldmatrix.sync.aligned.m8n8.x4.shared.b16 {%0,%1,%2,%3}, [%4];" \
                 : "=r"((r)[0]), "=r"((r)[1]), "=r"((r)[2]), "=r"((r)[3])        \
                 : "r"(addr))

#define MMA(d, a, b0, b1)                                                       \
    asm volatile("mma.sync.aligned.m16n8k16.row.col.f32.f16.f16.f32 "           \
                 "{%0,%1,%2,%3}, {%4,%5,%6,%7}, {%8,%9}, {%0,%1,%2,%3};"        \
                 : "+f"((d)[0]), "+f"((d)[1]), "+f"((d)[2]), "+f"((d)[3])        \
                 : "r"((a)[0]), "r"((a)[1]), "r"((a)[2]), "r"((a)[3]),           \
                   "r"(b0), "r"(b1))

extern __shared__ char smem_raw[];

// pure async copy: slab rows gh0..gh0+nrows-1 (pre-swizzled 128B rows)
__device__ __forceinline__ void build_rows_async(const unsigned char* __restrict__ xTb,
                                                 uint32_t sbs, int tid,
                                                 int gh0, int nrows) {
    const int total = nrows * 512;              // 16B chunks
    #pragma unroll
    for (int t = tid; t < total; t += 256) {
        int chunk = t & 7;
        int gw    = (t >> 3) & 63;
        int gh    = gh0 + (t >> 9);
        const unsigned char* src = xTb + ((size_t)gh * 64 + gw) * 128 + chunk * 16;
        uint32_t dst = sbs + (uint32_t)((((gh & 3) * 64 + gw) * 128) + chunk * 16);
        asm volatile("cp.async.cg.shared.global [%0], [%1], 16;"
                     :: "r"(dst), "l"(src));
    }
    asm volatile("cp.async.commit_group;");
}

__global__ void __launch_bounds__(256, 2)
conv_hmma_kernel(const float* __restrict__ k1,
                 const float* __restrict__ k2,
                 const float* __restrict__ x,
                 const float* __restrict__ bias,
                 float* __restrict__ out) {
    const int tid  = threadIdx.x;
    const int lane = tid & 31;
    const int wid  = tid >> 5;
    const int wm   = wid & 3;          // M block: oh = wm>>1, w-half = wm&1
    const int wn   = wid >> 2;         // N block: 32 filters
    const int fh   = blockIdx.x;       // filter half
    const int cid  = blockIdx.y;
    const int bid  = cid * 2 + fh;     // linear CTA id 0..295

    // ================= PHASE 0: cooperative prep (whole wave) =================
    // --- W: w = exp(k1)-exp(k2) -> fp16, swizzled [tap][f][c]; 1 elem/thread ---
    {
        int idx = bid * 256 + tid;                  // 75776 threads >= 73728
        if (idx < 73728) {
            int t   = idx >> 13;
            int rem = idx & 8191;
            int f   = rem >> 6;
            int c   = rem & 63;
            int src = (t * 64 + c) * 128 + f;       // k1 layout (kh,kw,C,F)
            float w = expf(k1[src]) - expf(k2[src]);
            __half h = __float2half_rn(w);
            unsigned off = (unsigned)(f * 128 + c * 2);
            off = off ^ ((off >> 3) & 0x70);        // SW128 swizzle
            *(unsigned short*)(g_W + t * 16384 + off) = *(unsigned short*)&h;
        }
    }
    // --- x: fp32 [bz][c][h][w] -> fp16 [bz][h][w][c] swizzled; <=7 slices/CTA ---
    {
        float (*tile)[65] = (float (*)[65])smem_raw;   // 16.6KB scratch in slab area
        #pragma unroll 1
        for (int s = 0; s < 7; s++) {
            int slice = bid * 7 + s;                // 2072 >= 2048
            if (slice >= 2048) break;
            int h  = slice & 63;
            int bz = slice >> 6;
            __syncthreads();
            #pragma unroll
            for (int i = 0; i < 16; i++) {
                int idx = tid + i * 256;
                int c = idx >> 6;
                int w = idx & 63;
                tile[c][w] = x[(((size_t)bz * 64 + c) * 64 + h) * 64 + w];
            }
            __syncthreads();
            unsigned char* dst = g_xT + (((size_t)bz * 64 + h) * 64) * 128;
            #pragma unroll
            for (int i = 0; i < 2; i++) {
                int t  = tid + i * 256;
                int w  = t >> 3;
                int cg = t & 7;
                unsigned short hs[8];
                #pragma unroll
                for (int k = 0; k < 8; k++) {
                    __half hv = __float2half_rn(tile[cg * 8 + k][w]);
                    hs[k] = *(unsigned short*)&hv;
                }
                unsigned off = (unsigned)(w * 128)
                             + (((unsigned)cg * 16) ^ (((unsigned)w & 7) << 4));
                *(uint4*)(dst + off) =
                    make_uint4((uint32_t)hs[0] | ((uint32_t)hs[1] << 16),
                               (uint32_t)hs[2] | ((uint32_t)hs[3] << 16),
                               (uint32_t)hs[4] | ((uint32_t)hs[5] << 16),
                               (uint32_t)hs[6] | ((uint32_t)hs[7] << 16));
            }
        }
    }
    __syncthreads();
    // --- grid barrier: monotonic generation counter (replay-safe) ---
    if (tid == 0) {
        __threadfence();
        unsigned my = atomicAdd(&g_bar, 1u);
        unsigned target = (my / NCTA_TOTAL + 1u) * NCTA_TOTAL;
        while (*(volatile unsigned*)&g_bar < target) { }
        __threadfence();
    }
    __syncthreads();

    // ================= PHASE 1: persistent HMMA conv (R14) =================
    const int jstart = cid * JOBS_PER_CTA;
    if (jstart >= JOBS_PER_HALF) return;
    const int jend = (jstart + JOBS_PER_CTA < JOBS_PER_HALF)
                   ? jstart + JOBS_PER_CTA : JOBS_PER_HALF;

    const uint32_t sb = smem_u32(smem_raw);

    // ---- resident weight load: 64 filters x 9 taps (72KB), once per CTA ----
    {
        const unsigned char* src = g_W + fh * 8192;
        #pragma unroll
        for (int j = 0; j < 18; j++) {
            int k = tid + j * 256;
            int tap = k >> 9;
            int rem = k & 511;
            asm volatile("cp.async.cg.shared.global [%0], [%1], 16;"
                         :: "r"(sb + WOFF + (uint32_t)k * 16),
                            "l"(src + (size_t)tap * 16384 + rem * 16));
        }
        asm volatile("cp.async.commit_group;");
    }

    // zero pad rows 256..257 (overflow target; feeds only discarded outputs)
    if (tid < 16) {
        *(uint4*)(smem_raw + 256 * 128 + tid * 16) = make_uint4(0u, 0u, 0u, 0u);
    }

    // ---- lane-constant addressing (A = W, B = x) ----
    const uint32_t a_hi16 = (uint32_t)(lane >> 4) * 16;            // k half
    const uint32_t swzAW  = (uint32_t)(lane & 7) << 4;
    const uint32_t wA     = sb + WOFF + (uint32_t)(wn * 32 + (lane & 15)) * 128;
    const int      wb0    = (wm & 1) * 32 + (lane & 7) + ((lane >> 4) & 1) * 8;
    const uint32_t bk16   = (uint32_t)((lane >> 3) & 1) * 16;      // k half

    // bias hoisted: f = fh*64 + wn*32 + mi*16 + (lane>>2) + half*8
    const int fb = fh * 64 + wn * 32 + (lane >> 2);
    float bv[2][2];
    #pragma unroll
    for (int mi = 0; mi < 2; mi++)
        #pragma unroll
        for (int hf = 0; hf < 2; hf++)
            bv[mi][hf] = __ldg(bias + fb + mi * 16 + hf * 8);

    // ---- build slab for first job (4 rows, async) ----
    int j0bz = jstart / 31;
    int j0ht = jstart - j0bz * 31;
    build_rows_async(g_xT + (size_t)j0bz * 64 * 64 * 128, sb, tid, 2 * j0ht, 4);

    #pragma unroll 1
    for (int j = jstart; j < jend; j++) {
        const int bz = j / 31;
        const int ht = j - bz * 31;
        const int h0 = 2 * ht;

        asm volatile("cp.async.wait_group 0;"); // weights + slab copies landed
        __syncthreads();                        // visible to all warps

        float acc[2][4][4];                     // [mi(f16)][ni(ow8)][quad]
        #pragma unroll
        for (int mi = 0; mi < 2; mi++)
            #pragma unroll
            for (int ni = 0; ni < 4; ni++)
                #pragma unroll
                for (int q = 0; q < 4; q++) acc[mi][ni][q] = 0.0f;

        // fragment double buffers (index = kc&1, statically resolved)
        uint32_t Af[2][2][4], Bf[2][2][4];

        // preamble: load step (t=0, kc=0) into buf 0
        {
            const int xrow = ((h0 + (wm >> 1)) & 3) * 64 + wb0;     // ki=0,kj=0
            const uint32_t swzB = (uint32_t)(lane & 7) << 4;
            const uint32_t bB   = sb + (uint32_t)xrow * 128;
            const uint32_t aoff = a_hi16 ^ swzAW;
            const uint32_t boff = bk16 ^ swzB;
            LDSM4(Af[0][0], wA + aoff);
            LDSM4(Af[0][1], wA + 2048 + aoff);
            LDSM4(Bf[0][0], bB + boff);
            LDSM4(Bf[0][1], bB + 2048 + boff);
        }

        #pragma unroll 1
        for (int t = 0; t < 9; t++) {
            const int ki = t / 3;
            const int kj = t - 3 * ki;
            const int xrow = ((h0 + (wm >> 1) + ki) & 3) * 64 + wb0 + kj;
            const uint32_t swzB  = (uint32_t)(((lane & 7) + kj) & 7) << 4;
            const uint32_t bBase = sb + (uint32_t)xrow * 128;
            const uint32_t aBase = wA + (uint32_t)t * 8192;

            const int tn  = (t < 8) ? t + 1 : 8;     // t=8: dummy self
            const int nki = tn / 3;
            const int nkj = tn - 3 * nki;
            const int nxr = ((h0 + (wm >> 1) + nki) & 3) * 64 + wb0 + nkj;
            const uint32_t nswzB  = (uint32_t)(((lane & 7) + nkj) & 7) << 4;
            const uint32_t nbBase = sb + (uint32_t)nxr * 128;
            const uint32_t naBase = wA + (uint32_t)tn * 8192;

            #pragma unroll
            for (int kc = 0; kc < 4; kc++) {
                const int cur = kc & 1;
                const int nxt = cur ^ 1;
                const uint32_t pa   = (kc < 3) ? aBase : naBase;
                const uint32_t pb   = (kc < 3) ? bBase : nbBase;
                const uint32_t pswz = (kc < 3) ? swzB  : nswzB;
                const uint32_t pkc  = (kc < 3) ? (uint32_t)((kc + 1) * 32) : 0u;
                const uint32_t aoffn = (pkc + a_hi16) ^ swzAW;
                const uint32_t boffn = (pkc + bk16) ^ pswz;
                LDSM4(Af[nxt][0], pa + aoffn);
                LDSM4(Af[nxt][1], pa + 2048 + aoffn);
                LDSM4(Bf[nxt][0], pb + boffn);
                LDSM4(Bf[nxt][1], pb + 2048 + boffn);

                #pragma unroll
                for (int mi = 0; mi < 2; mi++)
                    #pragma unroll
                    for (int wi = 0; wi < 2; wi++) {
                        MMA(acc[mi][2 * wi],     Af[cur][mi], Bf[cur][wi][0], Bf[cur][wi][1]);
                        MMA(acc[mi][2 * wi + 1], Af[cur][mi], Bf[cur][wi][2], Bf[cur][wi][3]);
                    }
            }
        }

        __syncthreads();               // all reads done; slab slots reusable

        // ---- async build for next job (overlaps epilogue) ----
        if (j + 1 < jend) {
            const int nbz = (j + 1) / 31;
            const int nht = (j + 1) - nbz * 31;
            const unsigned char* nxT = g_xT + (size_t)nbz * 64 * 64 * 128;
            if (nht != 0) build_rows_async(nxT, sb, tid, 2 * nht + 2, 2);
            else          build_rows_async(nxT, sb, tid, 0, 4);
        }

        // ---- epilogue: STG.64 of consecutive-ow pairs ----
        const int oh  = h0 + (wm >> 1);
        const int wpx = (wm & 1) * 32;
        #pragma unroll
        for (int mi = 0; mi < 2; mi++) {
            const int f0 = fb + mi * 16;
            float* p0 = out + (((size_t)bz * Fn + f0) * HOn + oh) * WOn;
            float* p1 = p0 + (size_t)8 * HOn * WOn;     // f0 + 8
            #pragma unroll
            for (int ni = 0; ni < 4; ni++) {
                const int ow = wpx + ni * 8 + (lane & 3) * 2;
                if (ow < WOn) {       // pair (62,63) dropped whole
                    float2 v0 = make_float2(acc[mi][ni][0] + bv[mi][0],
                                            acc[mi][ni][1] + bv[mi][0]);
                    float2 v1 = make_float2(acc[mi][ni][2] + bv[mi][1],
                                            acc[mi][ni][3] + bv[mi][1]);
                    *(float2*)(p0 + ow) = v0;
                    *(float2*)(p1 + ow) = v1;
                }
            }
        }
    }
}

extern "C" void kernel_launch(void* const* d_in, const int* in_sizes, int n_in,
                              void* d_out, int out_size) {
    const float* x    = (const float*)d_in[0];   // (32,64,64,64)
    const float* k1   = (const float*)d_in[1];   // (3,3,64,128)
    const float* k2   = (const float*)d_in[2];   // (3,3,64,128)
    const float* bias = (const float*)d_in[3];   // (128,)
    float* out = (float*)d_out;                  // (32,128,62,62)
    (void)in_sizes; (void)n_in; (void)out_size;

    cudaFuncSetAttribute(conv_hmma_kernel,
                         cudaFuncAttributeMaxDynamicSharedMemorySize, SMEM_TOTAL);

    dim3 grid(2, NCTA_PER_HALF);                 // 296 CTAs = one wave, 2/SM
    conv_hmma_kernel<<<grid, 256, SMEM_TOTAL>>>(k1, k2, x, bias, out);
}

// round 16
// speedup vs baseline: 1.0597x; 1.0597x over previous
#include <cuda_runtime.h>
#include <cuda_fp16.h>
#include <cstdint>

// MorphLayer == conv2d(x, exp(k1)-exp(k2), VALID 3x3) + bias  (exact reduction)
// B=32 C=64 H=W=64 -> Ho=Wo=62, F=128.
// HMMA implicit-GEMM, single fp16 product, fp32 acc.
// R16 = best-of-all-rounds consolidation:
//   - R14 mainloop: operands swapped (A=W, B=x), register double-buffered
//     fragment pipeline, STG.64 consecutive-ow epilogue
//   - R11 slab build: in-kernel LDG fp32 -> fp16 -> swizzled STS (no g_xT,
//     no prep_x kernel, no transpose pass)
//   - prep_w only, 72 blocks x 1024 threads (launch-overhead-minimized)

#define Hn  64
#define Wn  64
#define HOn 62
#define WOn 62
#define Fn  128
#define Cn  64

#define SLAB_ROWS  258                     // 4 ring slots * 64 + 2 pad rows
#define SLAB_BYTES (SLAB_ROWS * 128)       // 33024
#define WOFF       SLAB_BYTES
#define WRES_BYTES (9 * 64 * 128)          // 73728
#define SMEM_TOTAL (WOFF + WRES_BYTES)     // 106752 -> 2 CTAs/SM

#define JOBS_PER_HALF 992                  // 31 h-tiles * 32 batch
#define NCTA_PER_HALF 148
#define JOBS_PER_CTA  7

// fp16 weights, SW128-swizzled: [tap][f=128][c=64]
__device__ __align__(16) unsigned char g_W[9 * 16384];

__device__ __forceinline__ uint32_t smem_u32(const void* p) {
    uint32_t a;
    asm("{ .reg .u64 t; cvta.to.shared.u64 t, %1; cvt.u32.u64 %0, t; }" : "=r"(a) : "l"(p));
    return a;
}

#define LDSM4(r, addr)                                                          \
    asm volatile("ldmatrix.sync.aligned.m8n8.x4.shared.b16 {%0,%1,%2,%3}, [%4];" \
                 : "=r"((r)[0]), "=r"((r)[1]), "=r"((r)[2]), "=r"((r)[3])        \
                 : "r"(addr))

#define MMA(d, a, b0, b1)                                                       \
    asm volatile("mma.sync.aligned.m16n8k16.row.col.f32.f16.f16.f32 "           \
                 "{%0,%1,%2,%3}, {%4,%5,%6,%7}, {%8,%9}, {%0,%1,%2,%3};"        \
                 : "+f"((d)[0]), "+f"((d)[1]), "+f"((d)[2]), "+f"((d)[3])        \
                 : "r"((a)[0]), "r"((a)[1]), "r"((a)[2]), "r"((a)[3]),           \
                   "r"(b0), "r"(b1))

// ---------------- weight prep: w = exp(k1)-exp(k2) -> fp16, swizzled ----------------
__global__ void prep_w(const float* __restrict__ k1, const float* __restrict__ k2) {
    int idx = blockIdx.x * 1024 + threadIdx.x;      // 72 * 1024 = 73728 exact
    int t   = idx >> 13;
    int rem = idx & 8191;
    int f   = rem >> 6;
    int c   = rem & 63;
    int src = (t * 64 + c) * 128 + f;               // k1 layout (kh,kw,C,F)
    float w = expf(k1[src]) - expf(k2[src]);
    __half h = __float2half_rn(w);
    unsigned off = (unsigned)(f * 128 + c * 2);
    off = off ^ ((off >> 3) & 0x70);                // SW128 swizzle
    *(unsigned short*)(g_W + t * 16384 + off) = *(unsigned short*)&h;
}

// ---------------- main kernel ----------------
extern __shared__ char smem_raw[];

// in-kernel slab build: LDG fp32 (coalesced across lanes), cvt, swizzled STS.
// All gh are in-bounds by construction (h0 <= 60).
__device__ __forceinline__ void build_rows(const float* __restrict__ xb,
                                           char* smem, int tid,
                                           int gh0, int nrows) {
    #pragma unroll 1
    for (int it = 0; it < 2 * nrows; it++) {
        int t    = tid + it * 256;
        int gw   = t & 63;
        int cg   = (t >> 6) & 7;
        int gh   = gh0 + (t >> 9);
        const float* xp = xb + (size_t)(cg * 8) * (Hn * Wn) + gh * Wn + gw;
        unsigned short hs[8];
        #pragma unroll
        for (int i = 0; i < 8; i++) {
            __half h = __float2half_rn(xp[(size_t)i * (Hn * Wn)]);
            hs[i] = *(unsigned short*)&h;
        }
        unsigned row  = (unsigned)((gh & 3) * 64 + gw);     // ring slot
        unsigned boff = row * 128 + cg * 16;
        unsigned sw   = boff ^ ((boff >> 3) & 0x70);
        *(uint4*)(smem + sw) =
            make_uint4((uint32_t)hs[0] | ((uint32_t)hs[1] << 16),
                       (uint32_t)hs[2] | ((uint32_t)hs[3] << 16),
                       (uint32_t)hs[4] | ((uint32_t)hs[5] << 16),
                       (uint32_t)hs[6] | ((uint32_t)hs[7] << 16));
    }
}

__global__ void __launch_bounds__(256, 2)
conv_hmma_kernel(const float* __restrict__ x,
                 const float* __restrict__ bias,
                 float* __restrict__ out) {
    const int tid  = threadIdx.x;
    const int lane = tid & 31;
    const int wid  = tid >> 5;
    const int wm   = wid & 3;          // M block: oh = wm>>1, w-half = wm&1
    const int wn   = wid >> 2;         // N block: 32 filters
    const int fh   = blockIdx.x;       // filter half
    const int cid  = blockIdx.y;

    const int jstart = cid * JOBS_PER_CTA;
    if (jstart >= JOBS_PER_HALF) return;
    const int jend = (jstart + JOBS_PER_CTA < JOBS_PER_HALF)
                   ? jstart + JOBS_PER_CTA : JOBS_PER_HALF;

    const uint32_t sb = smem_u32(smem_raw);

    // ---- resident weight load: 64 filters x 9 taps (72KB), once per CTA ----
    {
        const unsigned char* src = g_W + fh * 8192;
        #pragma unroll
        for (int j = 0; j < 18; j++) {
            int k = tid + j * 256;
            int tap = k >> 9;
            int rem = k & 511;
            asm volatile("cp.async.cg.shared.global [%0], [%1], 16;"
                         :: "r"(sb + WOFF + (uint32_t)k * 16),
                            "l"(src + (size_t)tap * 16384 + rem * 16));
        }
        asm volatile("cp.async.commit_group;");
    }

    // zero pad rows 256..257 (overflow target; feeds only discarded outputs)
    if (tid < 16) {
        *(uint4*)(smem_raw + 256 * 128 + tid * 16) = make_uint4(0u, 0u, 0u, 0u);
    }

    // ---- lane-constant addressing (A = W, B = x) ----
    const uint32_t a_hi16 = (uint32_t)(lane >> 4) * 16;            // k half
    const uint32_t swzAW  = (uint32_t)(lane & 7) << 4;
    const uint32_t wA     = sb + WOFF + (uint32_t)(wn * 32 + (lane & 15)) * 128;
    const int      wb0    = (wm & 1) * 32 + (lane & 7) + ((lane >> 4) & 1) * 8;
    const uint32_t bk16   = (uint32_t)((lane >> 3) & 1) * 16;      // k half

    // bias hoisted: f = fh*64 + wn*32 + mi*16 + (lane>>2) + half*8
    const int fb = fh * 64 + wn * 32 + (lane >> 2);
    float bv[2][2];
    #pragma unroll
    for (int mi = 0; mi < 2; mi++)
        #pragma unroll
        for (int hf = 0; hf < 2; hf++)
            bv[mi][hf] = __ldg(bias + fb + mi * 16 + hf * 8);

    // ---- build slab for first job (4 rows, LDG+STS) ----
    int j0bz = jstart / 31;
    int j0ht = jstart - j0bz * 31;
    build_rows(x + (size_t)j0bz * Cn * Hn * Wn, smem_raw, tid, 2 * j0ht, 4);

    asm volatile("cp.async.wait_group 0;");   // resident weights landed

    #pragma unroll 1
    for (int j = jstart; j < jend; j++) {
        const int bz = j / 31;
        const int ht = j - bz * 31;
        const int h0 = 2 * ht;

        __syncthreads();                      // slab STS visible to all warps

        float acc[2][4][4];                   // [mi(f16)][ni(ow8)][quad]
        #pragma unroll
        for (int mi = 0; mi < 2; mi++)
            #pragma unroll
            for (int ni = 0; ni < 4; ni++)
                #pragma unroll
                for (int q = 0; q < 4; q++) acc[mi][ni][q] = 0.0f;

        // fragment double buffers (index = kc&1, statically resolved)
        uint32_t Af[2][2][4], Bf[2][2][4];

        // preamble: load step (t=0, kc=0) into buf 0
        {
            const int xrow = ((h0 + (wm >> 1)) & 3) * 64 + wb0;     // ki=0,kj=0
            const uint32_t swzB = (uint32_t)(lane & 7) << 4;
            const uint32_t bB   = sb + (uint32_t)xrow * 128;
            const uint32_t aoff = a_hi16 ^ swzAW;
            const uint32_t boff = bk16 ^ swzB;
            LDSM4(Af[0][0], wA + aoff);
            LDSM4(Af[0][1], wA + 2048 + aoff);
            LDSM4(Bf[0][0], bB + boff);
            LDSM4(Bf[0][1], bB + 2048 + boff);
        }

        #pragma unroll 1
        for (int t = 0; t < 9; t++) {
            const int ki = t / 3;
            const int kj = t - 3 * ki;
            const int xrow = ((h0 + (wm >> 1) + ki) & 3) * 64 + wb0 + kj;
            const uint32_t swzB  = (uint32_t)(((lane & 7) + kj) & 7) << 4;
            const uint32_t bBase = sb + (uint32_t)xrow * 128;
            const uint32_t aBase = wA + (uint32_t)t * 8192;

            const int tn  = (t < 8) ? t + 1 : 8;     // t=8: dummy self
            const int nki = tn / 3;
            const int nkj = tn - 3 * nki;
            const int nxr = ((h0 + (wm >> 1) + nki) & 3) * 64 + wb0 + nkj;
            const uint32_t nswzB  = (uint32_t)(((lane & 7) + nkj) & 7) << 4;
            const uint32_t nbBase = sb + (uint32_t)nxr * 128;
            const uint32_t naBase = wA + (uint32_t)tn * 8192;

            #pragma unroll
            for (int kc = 0; kc < 4; kc++) {
                const int cur = kc & 1;
                const int nxt = cur ^ 1;
                const uint32_t pa   = (kc < 3) ? aBase : naBase;
                const uint32_t pb   = (kc < 3) ? bBase : nbBase;
                const uint32_t pswz = (kc < 3) ? swzB  : nswzB;
                const uint32_t pkc  = (kc < 3) ? (uint32_t)((kc + 1) * 32) : 0u;
                const uint32_t aoffn = (pkc + a_hi16) ^ swzAW;
                const uint32_t boffn = (pkc + bk16) ^ pswz;
                LDSM4(Af[nxt][0], pa + aoffn);
                LDSM4(Af[nxt][1], pa + 2048 + aoffn);
                LDSM4(Bf[nxt][0], pb + boffn);
                LDSM4(Bf[nxt][1], pb + 2048 + boffn);

                #pragma unroll
                for (int mi = 0; mi < 2; mi++)
                    #pragma unroll
                    for (int wi = 0; wi < 2; wi++) {
                        MMA(acc[mi][2 * wi],     Af[cur][mi], Bf[cur][wi][0], Bf[cur][wi][1]);
                        MMA(acc[mi][2 * wi + 1], Af[cur][mi], Bf[cur][wi][2], Bf[cur][wi][3]);
                    }
            }
        }

        __syncthreads();               // all reads done; slab slots reusable

        // ---- build slab rows for next job (LDGs overlap epilogue) ----
        if (j + 1 < jend) {
            const int nbz = (j + 1) / 31;
            const int nht = (j + 1) - nbz * 31;
            const float* nxb = x + (size_t)nbz * Cn * Hn * Wn;
            if (nht != 0) build_rows(nxb, smem_raw, tid, 2 * nht + 2, 2);
            else          build_rows(nxb, smem_raw, tid, 0, 4);
        }

        // ---- epilogue: STG.64 of consecutive-ow pairs ----
        const int oh  = h0 + (wm >> 1);
        const int wpx = (wm & 1) * 32;
        #pragma unroll
        for (int mi = 0; mi < 2; mi++) {
            const int f0 = fb + mi * 16;
            float* p0 = out + (((size_t)bz * Fn + f0) * HOn + oh) * WOn;
            float* p1 = p0 + (size_t)8 * HOn * WOn;     // f0 + 8
            #pragma unroll
            for (int ni = 0; ni < 4; ni++) {
                const int ow = wpx + ni * 8 + (lane & 3) * 2;
                if (ow < WOn) {       // pair (62,63) dropped whole
                    float2 v0 = make_float2(acc[mi][ni][0] + bv[mi][0],
                                            acc[mi][ni][1] + bv[mi][0]);
                    float2 v1 = make_float2(acc[mi][ni][2] + bv[mi][1],
                                            acc[mi][ni][3] + bv[mi][1]);
                    *(float2*)(p0 + ow) = v0;
                    *(float2*)(p1 + ow) = v1;
                }
            }
        }
    }
}

extern "C" void kernel_launch(void* const* d_in, const int* in_sizes, int n_in,
                              void* d_out, int out_size) {
    const float* x    = (const float*)d_in[0];   // (32,64,64,64)
    const float* k1   = (const float*)d_in[1];   // (3,3,64,128)
    const float* k2   = (const float*)d_in[2];   // (3,3,64,128)
    const float* bias = (const float*)d_in[3];   // (128,)
    float* out = (float*)d_out;                  // (32,128,62,62)
    (void)in_sizes; (void)n_in; (void)out_size;

    cudaFuncSetAttribute(conv_hmma_kernel,
                         cudaFuncAttributeMaxDynamicSharedMemorySize, SMEM_TOTAL);

    prep_w<<<72, 1024>>>(k1, k2);
    dim3 grid(2, NCTA_PER_HALF);                 // 296 CTAs, 2/SM, one wave
    conv_hmma_kernel<<<grid, 256, SMEM_TOTAL>>>(x, bias, out);
}